// round 1
// baseline (speedup 1.0000x reference)
#include <cuda_runtime.h>
#include <cstdint>

#define N_NODES 50000
#define N_EDGES 1600000
#define IN_DIM 64
#define HD 64          // NUM_HEADS * OUT_DIM
#define NUM_HEADS 4
#define OUT_DIM 16

// ---------------- device scratch (no allocations allowed) ----------------
__device__ float g_Q[N_NODES * HD];
__device__ float g_K[N_NODES * HD];
__device__ float g_V[N_NODES * HD];
__device__ float g_Z[N_NODES * NUM_HEADS];

// ---------------- helpers ----------------
__device__ __forceinline__ void red_add_v4(float* p, float a, float b, float c, float d) {
    asm volatile("red.global.add.v4.f32 [%0], {%1,%2,%3,%4};"
                 :: "l"(p), "f"(a), "f"(b), "f"(c), "f"(d) : "memory");
}

// ---------------- zero init ----------------
__global__ void zero_kernel(float* __restrict__ out) {
    int i = blockIdx.x * blockDim.x + threadIdx.x;
    if (i < N_NODES * HD) out[i] = 0.0f;
    if (i < N_NODES * NUM_HEADS) g_Z[i] = 0.0f;
}

// ---------------- node projections: out = x @ W + b (one of Q/K/V per blockIdx.y) ----
// Tile: 128 nodes x 64 dims, 128 threads, 8x8 micro-tile per thread.
#define PROJ_SMEM_FLOATS (128 * 65 + 64 * 64 + 64)
__global__ __launch_bounds__(128)
void proj_kernel(const float* __restrict__ x,
                 const float* __restrict__ WQ, const float* __restrict__ bQ,
                 const float* __restrict__ WK, const float* __restrict__ bK,
                 const float* __restrict__ WV, const float* __restrict__ bV) {
    const float* W;
    const float* b;
    float* out;
    if (blockIdx.y == 0)      { W = WQ; b = bQ; out = g_Q; }
    else if (blockIdx.y == 1) { W = WK; b = bK; out = g_K; }
    else                      { W = WV; b = bV; out = g_V; }

    extern __shared__ float sm[];
    float* x_s = sm;                 // 128 * 65
    float* w_s = sm + 128 * 65;      // 64 * 64
    float* b_s = w_s + 64 * 64;      // 64

    const int tid = threadIdx.x;
    const int base = blockIdx.x * 128;

    // load W (16 KB) as float4
    {
        const float4* W4 = reinterpret_cast<const float4*>(W);
        float4* ws4 = reinterpret_cast<float4*>(w_s);
        #pragma unroll
        for (int i = tid; i < 1024; i += 128) ws4[i] = W4[i];
    }
    if (tid < 64) b_s[tid] = b[tid];

    // load x tile with stride-65 padding
    for (int f = tid; f < 128 * 16; f += 128) {
        int r = f >> 4, q = f & 15;
        int gr = base + r;
        if (gr >= N_NODES) gr = N_NODES - 1;  // clamp (writes guarded later)
        float4 v = reinterpret_cast<const float4*>(x + (size_t)gr * 64)[q];
        float* d = x_s + r * 65 + q * 4;
        d[0] = v.x; d[1] = v.y; d[2] = v.z; d[3] = v.w;
    }
    __syncthreads();

    const int eg = tid >> 3;  // node group 0..15
    const int dg = tid & 7;   // dim group 0..7

    float acc[8][8];
    #pragma unroll
    for (int i = 0; i < 8; i++)
        #pragma unroll
        for (int j = 0; j < 8; j++) acc[i][j] = 0.0f;

    const float4* ws4 = reinterpret_cast<const float4*>(w_s);
    #pragma unroll 4
    for (int c = 0; c < 64; c++) {
        float4 w0 = ws4[c * 16 + dg * 2];
        float4 w1 = ws4[c * 16 + dg * 2 + 1];
        float a[8];
        #pragma unroll
        for (int i = 0; i < 8; i++) a[i] = x_s[(eg * 8 + i) * 65 + c];
        #pragma unroll
        for (int i = 0; i < 8; i++) {
            acc[i][0] += a[i] * w0.x; acc[i][1] += a[i] * w0.y;
            acc[i][2] += a[i] * w0.z; acc[i][3] += a[i] * w0.w;
            acc[i][4] += a[i] * w1.x; acc[i][5] += a[i] * w1.y;
            acc[i][6] += a[i] * w1.z; acc[i][7] += a[i] * w1.w;
        }
    }

    float b0 = b_s[dg * 8 + 0], b1 = b_s[dg * 8 + 1], b2 = b_s[dg * 8 + 2], b3 = b_s[dg * 8 + 3];
    float b4 = b_s[dg * 8 + 4], b5 = b_s[dg * 8 + 5], b6 = b_s[dg * 8 + 6], b7 = b_s[dg * 8 + 7];
    #pragma unroll
    for (int i = 0; i < 8; i++) {
        int n = base + eg * 8 + i;
        if (n < N_NODES) {
            float4 o0 = make_float4(acc[i][0] + b0, acc[i][1] + b1, acc[i][2] + b2, acc[i][3] + b3);
            float4 o1 = make_float4(acc[i][4] + b4, acc[i][5] + b5, acc[i][6] + b6, acc[i][7] + b7);
            float4* dst = reinterpret_cast<float4*>(out + (size_t)n * 64 + dg * 8);
            dst[0] = o0; dst[1] = o1;
        }
    }
}

// ---------------- fused edge kernel ----------------
// Per block: 128 edges. Phase A: E_tile = ea_tile @ WE + bE (8x8 micro-tile GEMM).
// Phase B: per (edge, head): score = exp(clip(0.25 * sum_d K[src]Q[dst]E, -5, 5));
//          red.add V[src]*score into out[dst], score into Z[dst].
#define EDGE_SMEM_FLOATS (128 * 65 + 64 * 64 + 64 + 128 * 68)
__global__ __launch_bounds__(128)
void edge_kernel(const float* __restrict__ ea,
                 const int* __restrict__ eidx,
                 const float* __restrict__ WE, const float* __restrict__ bE,
                 float* __restrict__ out) {
    extern __shared__ float sm[];
    float* ea_s = sm;                          // 128 * 65
    float* we_s = ea_s + 128 * 65;             // 64 * 64
    float* be_s = we_s + 64 * 64;              // 64
    float* E_s  = be_s + 64;                   // 128 * 68

    const int tid = threadIdx.x;
    const int base = blockIdx.x * 128;

    // load WE
    {
        const float4* W4 = reinterpret_cast<const float4*>(WE);
        float4* ws4 = reinterpret_cast<float4*>(we_s);
        #pragma unroll
        for (int i = tid; i < 1024; i += 128) ws4[i] = W4[i];
    }
    if (tid < 64) be_s[tid] = bE[tid];

    // load edge_attr tile (rows contiguous), store stride-65
    for (int f = tid; f < 128 * 16; f += 128) {
        int e = f >> 4, q = f & 15;
        float4 v = reinterpret_cast<const float4*>(ea + (size_t)(base + e) * 64)[q];
        float* d = ea_s + e * 65 + q * 4;
        d[0] = v.x; d[1] = v.y; d[2] = v.z; d[3] = v.w;
    }
    __syncthreads();

    // ---- Phase A: GEMM ----
    const int eg = tid >> 3;  // edge group 0..15
    const int dg = tid & 7;   // dim group 0..7

    float acc[8][8];
    #pragma unroll
    for (int i = 0; i < 8; i++)
        #pragma unroll
        for (int j = 0; j < 8; j++) acc[i][j] = 0.0f;

    const float4* ws4 = reinterpret_cast<const float4*>(we_s);
    #pragma unroll 4
    for (int c = 0; c < 64; c++) {
        float4 w0 = ws4[c * 16 + dg * 2];
        float4 w1 = ws4[c * 16 + dg * 2 + 1];
        float a[8];
        #pragma unroll
        for (int i = 0; i < 8; i++) a[i] = ea_s[(eg * 8 + i) * 65 + c];
        #pragma unroll
        for (int i = 0; i < 8; i++) {
            acc[i][0] += a[i] * w0.x; acc[i][1] += a[i] * w0.y;
            acc[i][2] += a[i] * w0.z; acc[i][3] += a[i] * w0.w;
            acc[i][4] += a[i] * w1.x; acc[i][5] += a[i] * w1.y;
            acc[i][6] += a[i] * w1.z; acc[i][7] += a[i] * w1.w;
        }
    }

    // add bias, stash to E_s (stride 68, float4-aligned)
    {
        float b0 = be_s[dg * 8 + 0], b1 = be_s[dg * 8 + 1], b2 = be_s[dg * 8 + 2], b3 = be_s[dg * 8 + 3];
        float b4 = be_s[dg * 8 + 4], b5 = be_s[dg * 8 + 5], b6 = be_s[dg * 8 + 6], b7 = be_s[dg * 8 + 7];
        #pragma unroll
        for (int i = 0; i < 8; i++) {
            float4* dst = reinterpret_cast<float4*>(E_s + (eg * 8 + i) * 68 + dg * 8);
            dst[0] = make_float4(acc[i][0] + b0, acc[i][1] + b1, acc[i][2] + b2, acc[i][3] + b3);
            dst[1] = make_float4(acc[i][4] + b4, acc[i][5] + b5, acc[i][6] + b6, acc[i][7] + b7);
        }
    }
    __syncthreads();

    // ---- Phase B: score + scatter. 4 threads per edge (one per head), 4 passes. ----
    #pragma unroll
    for (int pass = 0; pass < 4; pass++) {
        const int le = pass * 32 + (tid >> 2);   // local edge 0..127
        const int h  = tid & 3;                   // head
        const int ge = base + le;
        const int src = eidx[ge];
        const int dst = eidx[N_EDGES + ge];

        const float4* Kp = reinterpret_cast<const float4*>(g_K + (size_t)src * 64 + h * 16);
        const float4* Qp = reinterpret_cast<const float4*>(g_Q + (size_t)dst * 64 + h * 16);
        const float4* Ep = reinterpret_cast<const float4*>(E_s + le * 68 + h * 16);

        float s = 0.0f;
        #pragma unroll
        for (int q = 0; q < 4; q++) {
            float4 k = Kp[q];
            float4 qv = Qp[q];
            float4 e = Ep[q];
            s += k.x * qv.x * e.x + k.y * qv.y * e.y + k.z * qv.z * e.z + k.w * qv.w * e.w;
        }
        s *= 0.25f;  // 1/sqrt(16)
        s = fminf(fmaxf(s, -5.0f), 5.0f);
        s = __expf(s);

        const float4* Vp = reinterpret_cast<const float4*>(g_V + (size_t)src * 64 + h * 16);
        float* ob = out + (size_t)dst * 64 + h * 16;
        #pragma unroll
        for (int q = 0; q < 4; q++) {
            float4 v = Vp[q];
            red_add_v4(ob + q * 4, v.x * s, v.y * s, v.z * s, v.w * s);
        }
        atomicAdd(g_Z + (size_t)dst * 4 + h, s);
    }
}

// ---------------- finalize: out = wV / (Z + 1e-6) ----------------
__global__ void finalize_kernel(float* __restrict__ out) {
    int i = blockIdx.x * blockDim.x + threadIdx.x;
    if (i < N_NODES * HD) {
        int n = i >> 6;
        int h = (i >> 4) & 3;
        out[i] = out[i] / (g_Z[n * 4 + h] + 1e-6f);
    }
}

// ---------------- launch ----------------
extern "C" void kernel_launch(void* const* d_in, const int* in_sizes, int n_in,
                              void* d_out, int out_size) {
    const float* x   = (const float*)d_in[0];
    const float* ea  = (const float*)d_in[1];
    const int*   ei  = (const int*)  d_in[2];
    const float* WQ  = (const float*)d_in[3];
    const float* bQ  = (const float*)d_in[4];
    const float* WK  = (const float*)d_in[5];
    const float* bK  = (const float*)d_in[6];
    const float* WE  = (const float*)d_in[7];
    const float* bE  = (const float*)d_in[8];
    const float* WV  = (const float*)d_in[9];
    const float* bV  = (const float*)d_in[10];
    float* out = (float*)d_out;

    static_assert(EDGE_SMEM_FLOATS * 4 < 228 * 1024, "smem");
    cudaFuncSetAttribute(edge_kernel, cudaFuncAttributeMaxDynamicSharedMemorySize,
                         EDGE_SMEM_FLOATS * (int)sizeof(float));
    cudaFuncSetAttribute(proj_kernel, cudaFuncAttributeMaxDynamicSharedMemorySize,
                         PROJ_SMEM_FLOATS * (int)sizeof(float));

    // 1) zero output + Z
    {
        int total = N_NODES * HD;
        zero_kernel<<<(total + 255) / 256, 256>>>(out);
    }
    // 2) Q/K/V projections
    {
        dim3 grid((N_NODES + 127) / 128, 3);
        proj_kernel<<<grid, 128, PROJ_SMEM_FLOATS * sizeof(float)>>>(x, WQ, bQ, WK, bK, WV, bV);
    }
    // 3) fused edge GEMM + attention + scatter
    {
        edge_kernel<<<N_EDGES / 128, 128, EDGE_SMEM_FLOATS * sizeof(float)>>>(ea, ei, WE, bE, out);
    }
    // 4) finalize
    {
        int total = N_NODES * HD;
        finalize_kernel<<<(total + 255) / 256, 256>>>(out);
    }
}